// round 15
// baseline (speedup 1.0000x reference)
#include <cuda_runtime.h>
#include <cuda_fp16.h>
#include <mma.h>
#include <math.h>
#include <math_constants.h>
#include <cstdint>

using namespace nvcuda;

#define NP    30000
#define MPAD  30080          // 235 * 128
#define DIN   1536
#define DOUT  256
#define NE    320000
#define NEG_SLOPE 0.2f
#define N1    768            // xl1 | xr1 | res
#define N2    512            // xl2 | xr2
#define NCHUNK 4

// ---------------- scratch (device globals; no cudaMalloc allowed) -----------
__device__ __align__(256) __half g_x16[(size_t)MPAD * DIN];
__device__ __align__(256) __half g_w1[(size_t)DIN * N1];    // [K, N] fp16
__device__ __align__(256) __half g_w2[(size_t)DOUT * N2];   // [K, N] fp16
__device__ __align__(256) float g_b1[N1];                   // [b1l | b1r | resb]
__device__ __align__(256) float g_b2[N2];                   // [b2l | b2r]
__device__ __align__(256) __half g_y1h[(size_t)NP * 512];   // fp16 xl|xr layer1 (biased)
__device__ __align__(256) __half g_y2h[(size_t)NP * 512];   // fp16 xl|xr layer2 (biased)
__device__ __align__(256) float g_res[(size_t)NP * DOUT];   // fp32 residual proj (+resb)
__device__ __align__(256) float g_h1[(size_t)NP * DOUT];
__device__ __align__(256) __half g_h116[(size_t)MPAD * DOUT];

__device__ int g_deg[NP];
__device__ int g_off[NP + 1];
__device__ int g_cur[NP];
__device__ int g_srcs[NE];

// ---------------- helpers ----------------------------------------------------
__device__ __forceinline__ void cp16(void* dst, const void* src) {
    unsigned saddr = (unsigned)__cvta_generic_to_shared(dst);
    asm volatile("cp.async.cg.shared.global [%0], [%1], 16;\n" :: "r"(saddr), "l"(src));
}

// ---------------- weight/bias pack (small, main stream) ----------------------
#define PREPW_T2 (DIN * N1 / 4)
#define PREPW_T3 (DOUT * N2 / 4)
#define PREPW_T4 (N1 + N2)
#define PREPW_TOT (PREPW_T2 + PREPW_T3 + PREPW_T4)

__global__ void prep_w_kernel(const float* __restrict__ W1l,
                              const float* __restrict__ W1r,
                              const float* __restrict__ resW,
                              const float* __restrict__ W2l,
                              const float* __restrict__ W2r,
                              const float* __restrict__ b1l,
                              const float* __restrict__ b1r,
                              const float* __restrict__ resb,
                              const float* __restrict__ b2l,
                              const float* __restrict__ b2r) {
    int id = blockIdx.x * blockDim.x + threadIdx.x;
    if (id < PREPW_T2) {
        int i4 = id;
        int k = i4 / (N1 / 4);
        int c = (i4 % (N1 / 4)) * 4;
        const float* W = (c < 256) ? W1l : (c < 512 ? W1r : resW);
        int cc = c & 255;
        float4 v = *reinterpret_cast<const float4*>(W + (size_t)k * 256 + cc);
        size_t o = (size_t)k * N1 + c;
        g_w1[o+0] = __float2half_rn(v.x);
        g_w1[o+1] = __float2half_rn(v.y);
        g_w1[o+2] = __float2half_rn(v.z);
        g_w1[o+3] = __float2half_rn(v.w);
        return;
    }
    id -= PREPW_T2;
    if (id < PREPW_T3) {
        int i4 = id;
        int k = i4 / (N2 / 4);
        int c = (i4 % (N2 / 4)) * 4;
        const float* W = (c < 256) ? W2l : W2r;
        int cc = c & 255;
        float4 v = *reinterpret_cast<const float4*>(W + (size_t)k * 256 + cc);
        size_t o = (size_t)k * N2 + c;
        g_w2[o+0] = __float2half_rn(v.x);
        g_w2[o+1] = __float2half_rn(v.y);
        g_w2[o+2] = __float2half_rn(v.z);
        g_w2[o+3] = __float2half_rn(v.w);
        return;
    }
    id -= PREPW_T3;
    if (id < PREPW_T4) {
        int c = id;
        if (c < N1) {
            g_b1[c] = (c < 256) ? b1l[c] : (c < 512 ? b1r[c - 256] : resb[c - 512]);
        } else {
            int c2 = c - N1;
            g_b2[c2] = (c2 < 256) ? b2l[c2] : b2r[c2 - 256];
        }
    }
}

// ---------------- x -> fp16 conversion, row-chunked (pipeline stream) --------
__global__ void convert_x_chunk(const float* __restrict__ x, int r0, int nrows) {
    size_t i4 = (size_t)blockIdx.x * blockDim.x + threadIdx.x;
    const size_t tot = (size_t)nrows * (DIN / 4);
    if (i4 >= tot) return;
    size_t row = (size_t)r0 + i4 / (DIN / 4);
    size_t o = row * DIN + (i4 % (DIN / 4)) * 4;
    float4 v;
    if (row < NP) v = *reinterpret_cast<const float4*>(x + o);
    else          v = make_float4(0.f, 0.f, 0.f, 0.f);
    __half2 h0 = make_half2(__float2half_rn(v.x), __float2half_rn(v.y));
    __half2 h1 = make_half2(__float2half_rn(v.z), __float2half_rn(v.w));
    *reinterpret_cast<__half2*>(g_x16 + o)     = h0;
    *reinterpret_cast<__half2*>(g_x16 + o + 2) = h1;
}

// ---------------- fp16 tensor-core GEMM with fused bias+format epilogue ------
// Y[M,N] = A[M,K] @ B[K,N] + bias[N]; per column block: fp16 (col < nsplit) else fp32.
// CTA 128x128, BK=64, 128 threads = 4 warps (2M x 2N), warp tile 64x64,
// 3-stage cp.async, 105 KB smem -> 2 CTAs/SM. bm0 = row-chunk offset.
#define GBM 128
#define GBN 128
#define GBK 64
#define GTHREADS 128
#define LDA 72      // 64 + 8 pad (halfs)
#define LDB 136     // 128 + 8 pad
#define STG_A (128 * LDA)
#define STG_B (64 * LDB)
#define STAGE_ELEMS (STG_A + STG_B)
#define NSTAGE 3
#define GEMM_SMEM_BYTES (NSTAGE * STAGE_ELEMS * 2)   // 107520 B
#define LDY 136     // fp32 epilogue pitch; 128*136*4 = 69632 <= GEMM_SMEM_BYTES

__device__ __forceinline__ void gemm_load_stage(
    __half* st,
    const __half* __restrict__ A, const __half* __restrict__ B,
    int bm, int bn, int k0, int K, int N, int tid)
{
    __half* sA = st;
    __half* sB = st + STG_A;
#pragma unroll
    for (int c = 0; c < 8; c++) {
        int idx = tid + c * GTHREADS;
        int row = idx >> 3;
        int col = (idx & 7) * 8;
        size_t g = (size_t)(bm + row) * K + k0 + col;
        cp16(sA + row * LDA + col, A + g);
    }
#pragma unroll
    for (int c = 0; c < 8; c++) {
        int idx = tid + c * GTHREADS;
        int row = idx >> 4;
        int col = (idx & 15) * 8;
        size_t g = (size_t)(k0 + row) * N + bn + col;
        cp16(sB + row * LDB + col, B + g);
    }
    asm volatile("cp.async.commit_group;\n");
}

__global__ __launch_bounds__(GTHREADS, 2)
void gemm_h16(const __half* __restrict__ A,
              const __half* __restrict__ B,
              const float* __restrict__ bias,      // length N, added pre-convert
              __half* __restrict__ Yh, int ldh,    // fp16 out (cols < nsplit)
              float* __restrict__ Yf,              // fp32 out (cols >= nsplit)
              int nsplit, int K, int N, int bm0)
{
    extern __shared__ __half smem[];
    const int tid = threadIdx.x;
    const int bm = bm0 + blockIdx.y * GBM;
    const int bn = blockIdx.x * GBN;
    const int warp = tid >> 5;
    const int wm = (warp >> 1) * 64;   // 0 or 64
    const int wn = (warp & 1) * 64;    // 0 or 64

    wmma::fragment<wmma::accumulator, 16, 16, 16, float> acc[4][4];
#pragma unroll
    for (int i = 0; i < 4; i++)
#pragma unroll
        for (int j = 0; j < 4; j++) wmma::fill_fragment(acc[i][j], 0.f);

    const int KT = K / GBK;            // >= 4 for both GEMMs
    gemm_load_stage(smem + 0 * STAGE_ELEMS, A, B, bm, bn, 0 * GBK, K, N, tid);
    gemm_load_stage(smem + 1 * STAGE_ELEMS, A, B, bm, bn, 1 * GBK, K, N, tid);

    for (int kt = 0; kt < KT; kt++) {
        if (kt + 1 < KT) asm volatile("cp.async.wait_group 1;\n" ::: "memory");
        else             asm volatile("cp.async.wait_group 0;\n" ::: "memory");
        __syncthreads();
        if (kt + 2 < KT)
            gemm_load_stage(smem + ((kt + 2) % NSTAGE) * STAGE_ELEMS,
                            A, B, bm, bn, (kt + 2) * GBK, K, N, tid);

        __half* st = smem + (kt % NSTAGE) * STAGE_ELEMS;
        const __half* sA = st;
        const __half* sB = st + STG_A;

#pragma unroll
        for (int ks = 0; ks < 4; ks++) {
            wmma::fragment<wmma::matrix_a, 16, 16, 16, __half, wmma::row_major> fa[4];
#pragma unroll
            for (int i = 0; i < 4; i++)
                wmma::load_matrix_sync(fa[i], sA + (wm + i * 16) * LDA + ks * 16, LDA);
#pragma unroll
            for (int j = 0; j < 4; j++) {
                wmma::fragment<wmma::matrix_b, 16, 16, 16, __half, wmma::row_major> fb;
                wmma::load_matrix_sync(fb, sB + ks * 16 * LDB + wn + j * 16, LDB);
#pragma unroll
                for (int i = 0; i < 4; i++)
                    wmma::mma_sync(acc[i][j], fa[i], fb, acc[i][j]);
            }
        }
    }

    // ---- fused bias + format epilogue via smem staging ----
    __syncthreads();                         // all stage reads complete
    float* sY = reinterpret_cast<float*>(smem);
#pragma unroll
    for (int i = 0; i < 4; i++)
#pragma unroll
        for (int j = 0; j < 4; j++)
            wmma::store_matrix_sync(sY + (wm + i * 16) * LDY + wn + j * 16,
                                    acc[i][j], LDY, wmma::mem_row_major);
    __syncthreads();

    const bool f16 = (bn < nsplit);
#pragma unroll
    for (int c = 0; c < 16; c++) {
        int idx = tid + c * GTHREADS;        // 2048 chunks of 8 cols
        int row = idx >> 4;
        int col = (idx & 15) * 8;
        int grow = bm + row;
        if (grow >= NP) continue;            // pad rows never consumed
        const float* src = sY + row * LDY + col;
        float4 v0 = *reinterpret_cast<const float4*>(src);
        float4 v1 = *reinterpret_cast<const float4*>(src + 4);
        float4 b0 = *reinterpret_cast<const float4*>(bias + bn + col);
        float4 b1 = *reinterpret_cast<const float4*>(bias + bn + col + 4);
        v0.x += b0.x; v0.y += b0.y; v0.z += b0.z; v0.w += b0.w;
        v1.x += b1.x; v1.y += b1.y; v1.z += b1.z; v1.w += b1.w;
        if (f16) {
            __half2 h[4];
            h[0] = make_half2(__float2half_rn(v0.x), __float2half_rn(v0.y));
            h[1] = make_half2(__float2half_rn(v0.z), __float2half_rn(v0.w));
            h[2] = make_half2(__float2half_rn(v1.x), __float2half_rn(v1.y));
            h[3] = make_half2(__float2half_rn(v1.z), __float2half_rn(v1.w));
            *reinterpret_cast<uint4*>(Yh + (size_t)grow * ldh + bn + col) =
                *reinterpret_cast<uint4*>(h);
        } else {
            float* dst = Yf + (size_t)grow * DOUT + (bn - nsplit) + col;
            *reinterpret_cast<float4*>(dst)     = v0;
            *reinterpret_cast<float4*>(dst + 4) = v1;
        }
    }
}

// ---------------- CSR build --------------------------------------------------
__global__ void zero_deg_kernel() {
    int i = blockIdx.x * blockDim.x + threadIdx.x;
    if (i < NP) g_deg[i] = 0;
}

__global__ void count_deg_kernel(const int* __restrict__ dst) {
    int e = blockIdx.x * blockDim.x + threadIdx.x;
    if (e < NE) atomicAdd(&g_deg[dst[e]], 1);
}

__global__ void build_offsets_kernel() {
    __shared__ int ssum[1024];
    const int tid = threadIdx.x;
    const int CHK = (NP + 1023) / 1024;
    int start = tid * CHK;
    int end = start + CHK; if (end > NP) end = NP;
    if (start > NP) start = NP;

    int s = 0;
    for (int i = start; i < end; i++) s += g_deg[i];
    ssum[tid] = s;
    __syncthreads();
    for (int o = 1; o < 1024; o <<= 1) {
        int v = (tid >= o) ? ssum[tid - o] : 0;
        __syncthreads();
        ssum[tid] += v;
        __syncthreads();
    }
    int run = (tid == 0) ? 0 : ssum[tid - 1];
    for (int i = start; i < end; i++) {
        g_off[i] = run;
        g_cur[i] = run;
        run += g_deg[i];
    }
    if (tid == 1023) g_off[NP] = ssum[1023];
}

__global__ void scatter_edges_kernel(const int* __restrict__ src,
                                     const int* __restrict__ dst) {
    int e = blockIdx.x * blockDim.x + threadIdx.x;
    if (e < NE) {
        int d = dst[e];
        int pos = atomicAdd(&g_cur[d], 1);
        g_srcs[pos] = src[e];
    }
}

// ---------------- fused GATv2 gather + softmax + LN/ELU epilogue -------------
// Biases pre-folded into y*h by the GEMM epilogue. 4-edge unrolled online
// softmax (MLP=4).
__device__ __forceinline__ void load8h(const __half* p, float* f) {
    uint4 u = *reinterpret_cast<const uint4*>(p);
    const __half2* h = reinterpret_cast<const __half2*>(&u);
    float2 t;
    t = __half22float2(h[0]); f[0] = t.x; f[1] = t.y;
    t = __half22float2(h[1]); f[2] = t.x; f[3] = t.y;
    t = __half22float2(h[2]); f[4] = t.x; f[5] = t.y;
    t = __half22float2(h[3]); f[6] = t.x; f[7] = t.y;
}

__device__ __forceinline__ float edge_score(const float* xlj, const float* xri,
                                            const float* atv) {
    float p = 0.f;
#pragma unroll
    for (int k = 0; k < 8; k++) {
        float t = xlj[k] + xri[k];
        t = (t > 0.f) ? t : NEG_SLOPE * t;
        p = fmaf(atv[k], t, p);
    }
    p += __shfl_xor_sync(0xffffffffu, p, 8, 16);
    p += __shfl_xor_sync(0xffffffffu, p, 4, 16);
    p += __shfl_xor_sync(0xffffffffu, p, 2, 16);
    p += __shfl_xor_sync(0xffffffffu, p, 1, 16);
    return p;
}

__device__ __forceinline__ void gat_core(const __half* __restrict__ yh,
                                         const float* __restrict__ att,
                                         const float* __restrict__ bias,
                                         int i, int lane, float* v /*out[8]*/) {
    const int cbase = lane * 8;
    float xri[8], atv[8];
    {
        load8h(yh + (size_t)i * 512 + 256 + cbase, xri);   // biased xr[i]
        float4 t0 = *reinterpret_cast<const float4*>(att + cbase);
        float4 t1 = *reinterpret_cast<const float4*>(att + cbase + 4);
        atv[0]=t0.x; atv[1]=t0.y; atv[2]=t0.z; atv[3]=t0.w;
        atv[4]=t1.x; atv[5]=t1.y; atv[6]=t1.z; atv[7]=t1.w;
    }

    // init with self loop (biased xl[i])
    float m, s, acc[8];
    {
        float xls[8];
        load8h(yh + (size_t)i * 512 + cbase, xls);
        m = edge_score(xls, xri, atv);
        s = 1.f;
#pragma unroll
        for (int k = 0; k < 8; k++) acc[k] = xls[k];
    }

    int ptr = g_off[i];
    const int end = g_off[i + 1];

    for (; ptr + 4 <= end; ptr += 4) {
        int j0 = g_srcs[ptr + 0];
        int j1 = g_srcs[ptr + 1];
        int j2 = g_srcs[ptr + 2];
        int j3 = g_srcs[ptr + 3];
        uint4 u0 = *reinterpret_cast<const uint4*>(yh + (size_t)j0 * 512 + cbase);
        uint4 u1 = *reinterpret_cast<const uint4*>(yh + (size_t)j1 * 512 + cbase);
        uint4 u2 = *reinterpret_cast<const uint4*>(yh + (size_t)j2 * 512 + cbase);
        uint4 u3 = *reinterpret_cast<const uint4*>(yh + (size_t)j3 * 512 + cbase);
        float x0[8], x1[8], x2[8], x3[8];
        load8h(reinterpret_cast<const __half*>(&u0), x0);
        load8h(reinterpret_cast<const __half*>(&u1), x1);
        load8h(reinterpret_cast<const __half*>(&u2), x2);
        load8h(reinterpret_cast<const __half*>(&u3), x3);
        float e0 = edge_score(x0, xri, atv);
        float e1 = edge_score(x1, xri, atv);
        float e2 = edge_score(x2, xri, atv);
        float e3 = edge_score(x3, xri, atv);

        float nm = fmaxf(fmaxf(m, fmaxf(e0, e1)), fmaxf(e2, e3));
        float sc = __expf(m - nm);
        float w0 = __expf(e0 - nm);
        float w1 = __expf(e1 - nm);
        float w2 = __expf(e2 - nm);
        float w3 = __expf(e3 - nm);
        s = s * sc + (w0 + w1) + (w2 + w3);
#pragma unroll
        for (int k = 0; k < 8; k++) {
            float t = fmaf(w0, x0[k], w1 * x1[k]) + fmaf(w2, x2[k], w3 * x3[k]);
            acc[k] = fmaf(acc[k], sc, t);
        }
        m = nm;
    }
    for (; ptr < end; ptr++) {
        int j0 = g_srcs[ptr];
        float x0[8];
        load8h(yh + (size_t)j0 * 512 + cbase, x0);
        float e0 = edge_score(x0, xri, atv);
        float nm = fmaxf(m, e0);
        float sc = __expf(m - nm);
        float w0 = __expf(e0 - nm);
        s = s * sc + w0;
#pragma unroll
        for (int k = 0; k < 8; k++) acc[k] = fmaf(acc[k], sc, w0 * x0[k]);
        m = nm;
    }

    float inv = 1.f / s;
#pragma unroll
    for (int k = 0; k < 8; k++)
        v[k] = acc[k] * inv + bias[cbase + k];   // attention output bias
}

__device__ __forceinline__ void ln_elu_inplace(float* v,
                                               const float* __restrict__ g,
                                               const float* __restrict__ b,
                                               int lane) {
    float s = 0.f, s2 = 0.f;
#pragma unroll
    for (int k = 0; k < 8; k++) { s += v[k]; s2 = fmaf(v[k], v[k], s2); }
#pragma unroll
    for (int o = 16; o >= 1; o >>= 1) {
        s  += __shfl_xor_sync(0xffffffffu, s,  o);
        s2 += __shfl_xor_sync(0xffffffffu, s2, o);
    }
    float mu  = s * (1.f / 256.f);
    float var = s2 * (1.f / 256.f) - mu * mu;
    float rs  = rsqrtf(var + 1e-5f);
#pragma unroll
    for (int k = 0; k < 8; k++) {
        int c = lane * 8 + k;
        float t = (v[k] - mu) * rs * g[c] + b[c];
        v[k] = (t > 0.f) ? t : expm1f(t);
    }
}

// layer 1: gather -> LN -> ELU -> + res (resb folded) -> h1; pad rows zeroed
__global__ void gat1_kernel(const float* __restrict__ res,
                            const float* __restrict__ att,
                            const float* __restrict__ bias,
                            const float* __restrict__ lng,
                            const float* __restrict__ lnb,
                            float* __restrict__ h1,
                            __half* __restrict__ h116) {
    int w = (blockIdx.x * blockDim.x + threadIdx.x) >> 5;
    int lane = threadIdx.x & 31;
    if (w >= MPAD) return;
    const int cbase = lane * 8;
    if (w >= NP) {      // zero the GEMM2 pad rows
#pragma unroll
        for (int k = 0; k < 8; k++)
            h116[(size_t)w * DOUT + cbase + k] = __float2half_rn(0.f);
        return;
    }
    float v[8];
    gat_core(g_y1h, att, bias, w, lane, v);
    ln_elu_inplace(v, lng, lnb, lane);
#pragma unroll
    for (int k = 0; k < 8; k++) {
        size_t idx = (size_t)w * DOUT + cbase + k;
        float hv = v[k] + res[idx];
        h1[idx] = hv;
        h116[idx] = __float2half_rn(hv);
    }
}

// layer 2: gather -> LN -> ELU -> + h1 -> JK max
__global__ void gat2_kernel(const float* __restrict__ att,
                            const float* __restrict__ bias,
                            const float* __restrict__ lng,
                            const float* __restrict__ lnb,
                            const float* __restrict__ h1,
                            float* __restrict__ out) {
    int w = (blockIdx.x * blockDim.x + threadIdx.x) >> 5;
    int lane = threadIdx.x & 31;
    if (w >= NP) return;
    float v[8];
    gat_core(g_y2h, att, bias, w, lane, v);
    ln_elu_inplace(v, lng, lnb, lane);
    const int cbase = lane * 8;
#pragma unroll
    for (int k = 0; k < 8; k++) {
        size_t idx = (size_t)w * DOUT + cbase + k;
        float h1v = h1[idx];
        out[idx] = fmaxf(h1v, v[k] + h1v);
    }
}

// ---------------- launch -----------------------------------------------------
extern "C" void kernel_launch(void* const* d_in, const int* in_sizes, int n_in,
                              void* d_out, int out_size) {
    const float* x     = (const float*)d_in[0];
    const int*   ei    = (const int*)  d_in[1];
    const float* W1l   = (const float*)d_in[2];
    const float* b1l   = (const float*)d_in[3];
    const float* W1r   = (const float*)d_in[4];
    const float* b1r   = (const float*)d_in[5];
    const float* att1  = (const float*)d_in[6];
    const float* bias1 = (const float*)d_in[7];
    const float* W2l   = (const float*)d_in[8];
    const float* b2l   = (const float*)d_in[9];
    const float* W2r   = (const float*)d_in[10];
    const float* b2r   = (const float*)d_in[11];
    const float* att2  = (const float*)d_in[12];
    const float* bias2 = (const float*)d_in[13];
    const float* ln1g  = (const float*)d_in[14];
    const float* ln1b  = (const float*)d_in[15];
    const float* ln2g  = (const float*)d_in[16];
    const float* ln2b  = (const float*)d_in[17];
    const float* resW  = (const float*)d_in[18];
    const float* resb  = (const float*)d_in[19];
    float* out = (float*)d_out;

    const int* e_src = ei;
    const int* e_dst = ei + NE;

    __half *x16, *w1, *w2, *h116, *y1h, *y2h;
    float *res, *h1, *bv1, *bv2;
    cudaGetSymbolAddress((void**)&x16,  g_x16);
    cudaGetSymbolAddress((void**)&w1,   g_w1);
    cudaGetSymbolAddress((void**)&w2,   g_w2);
    cudaGetSymbolAddress((void**)&h116, g_h116);
    cudaGetSymbolAddress((void**)&y1h,  g_y1h);
    cudaGetSymbolAddress((void**)&y2h,  g_y2h);
    cudaGetSymbolAddress((void**)&res,  g_res);
    cudaGetSymbolAddress((void**)&h1,   g_h1);
    cudaGetSymbolAddress((void**)&bv1,  g_b1);
    cudaGetSymbolAddress((void**)&bv2,  g_b2);

    cudaFuncSetAttribute(gemm_h16, cudaFuncAttributeMaxDynamicSharedMemorySize,
                         GEMM_SMEM_BYTES);

    // one-time handles (host-side only; identical launched work every call)
    static cudaStream_t s2 = [] { cudaStream_t s; cudaStreamCreateWithFlags(&s, cudaStreamNonBlocking); return s; }();
    static cudaStream_t s3 = [] { cudaStream_t s; cudaStreamCreateWithFlags(&s, cudaStreamNonBlocking); return s; }();
    static cudaEvent_t  e1 = [] { cudaEvent_t e; cudaEventCreateWithFlags(&e, cudaEventDisableTiming); return e; }();
    static cudaEvent_t  e2 = [] { cudaEvent_t e; cudaEventCreateWithFlags(&e, cudaEventDisableTiming); return e; }();
    static cudaEvent_t  ec[NCHUNK] = {
        [] { cudaEvent_t e; cudaEventCreateWithFlags(&e, cudaEventDisableTiming); return e; }(),
        [] { cudaEvent_t e; cudaEventCreateWithFlags(&e, cudaEventDisableTiming); return e; }(),
        [] { cudaEvent_t e; cudaEventCreateWithFlags(&e, cudaEventDisableTiming); return e; }(),
        [] { cudaEvent_t e; cudaEventCreateWithFlags(&e, cudaEventDisableTiming); return e; }() };

    // row-chunk partition (multiples of 128): 59+59+59+58 blocks = 235
    static const int chunkBlk[NCHUNK] = {59, 59, 59, 58};
    static const int chunkR0 [NCHUNK] = {0, 59 * 128, 118 * 128, 177 * 128};

    // ---- fork point ----
    cudaEventRecord(e1, 0);
    cudaStreamWaitEvent(s2, e1, 0);
    cudaStreamWaitEvent(s3, e1, 0);

    // CSR chain on s2 (joined before gat1)
    zero_deg_kernel<<<(NP + 255) / 256, 256, 0, s2>>>();
    count_deg_kernel<<<(NE + 255) / 256, 256, 0, s2>>>(e_dst);
    build_offsets_kernel<<<1, 1024, 0, s2>>>();
    scatter_edges_kernel<<<(NE + 255) / 256, 256, 0, s2>>>(e_src, e_dst);
    cudaEventRecord(e2, s2);

    // x->fp16 conversion chunks on s3
    for (int c = 0; c < NCHUNK; c++) {
        int nrows = chunkBlk[c] * 128;
        size_t tot = (size_t)nrows * (DIN / 4);
        convert_x_chunk<<<(unsigned)((tot + 255) / 256), 256, 0, s3>>>(x, chunkR0[c], nrows);
        cudaEventRecord(ec[c], s3);
    }

    // main stream: W/bias pack, then GEMM1 row-chunks gated on their converts
    prep_w_kernel<<<(PREPW_TOT + 255) / 256, 256>>>(
        W1l, W1r, resW, W2l, W2r, b1l, b1r, resb, b2l, b2r);
    for (int c = 0; c < NCHUNK; c++) {
        cudaStreamWaitEvent(0, ec[c], 0);
        gemm_h16<<<dim3(N1 / GBN, chunkBlk[c]), GTHREADS, GEMM_SMEM_BYTES>>>(
            x16, w1, bv1, y1h, 512, res, 512, DIN, N1, chunkR0[c]);
    }

    // join: gat1 needs the CSR
    cudaStreamWaitEvent(0, e2, 0);

    int gather1Blocks = (MPAD * 32 + 255) / 256;
    int gather2Blocks = (NP * 32 + 255) / 256;
    gat1_kernel<<<gather1Blocks, 256>>>(res, att1, bias1, ln1g, ln1b, h1, h116);

    // layer-2 fused GEMM: all cols -> fp16 g_y2h (biases folded)
    gemm_h16<<<dim3(N2 / GBN, MPAD / GBM), GTHREADS, GEMM_SMEM_BYTES>>>(
        h116, w2, bv2, y2h, 512, (float*)nullptr, 512, DOUT, N2, 0);

    // layer-2 gather + LN/ELU + JK-max (fused)
    gat2_kernel<<<gather2Blocks, 256>>>(att2, bias2, ln2g, ln2b, h1, out);
}

// round 16
// speedup vs baseline: 1.1819x; 1.1819x over previous
#include <cuda_runtime.h>
#include <cuda_fp16.h>
#include <mma.h>
#include <math.h>
#include <math_constants.h>
#include <cstdint>

using namespace nvcuda;

#define NP    30000
#define MPAD  30080          // 235 * 128
#define DIN   1536
#define DOUT  256
#define NE    320000
#define NEG_SLOPE 0.2f
#define N1    768            // xl1 | xr1 | res
#define N2    512            // xl2 | xr2

// ---------------- scratch (device globals; no cudaMalloc allowed) -----------
__device__ __align__(256) __half g_x16[(size_t)MPAD * DIN];
__device__ __align__(256) __half g_w1[(size_t)DIN * N1];    // [K, N] fp16
__device__ __align__(256) __half g_w2[(size_t)DOUT * N2];   // [K, N] fp16
__device__ __align__(256) float g_b1[N1];                   // [b1l | b1r | resb]
__device__ __align__(256) float g_b2[N2];                   // [b2l | b2r]
__device__ __align__(256) __half g_y1h[(size_t)NP * N1];    // fp16 xl|xr|res (biased)
__device__ __align__(256) __half g_y2h[(size_t)NP * N2];    // fp16 xl|xr (biased)
__device__ __align__(256) __half g_h116[(size_t)MPAD * DOUT];

__device__ int g_deg[NP];
__device__ int g_off[NP + 1];
__device__ int g_cur[NP];
__device__ int g_srcs[NE];

// ---------------- helpers ----------------------------------------------------
__device__ __forceinline__ void cp16(void* dst, const void* src) {
    unsigned saddr = (unsigned)__cvta_generic_to_shared(dst);
    asm volatile("cp.async.cg.shared.global [%0], [%1], 16;\n" :: "r"(saddr), "l"(src));
}

// ---------------- merged prep kernel (R14 layout: single launch) -------------
#define PREP_T1 ((size_t)MPAD * DIN / 4)
#define PREP_T2 (DIN * N1 / 4)
#define PREP_T3 (DOUT * N2 / 4)
#define PREP_T4 (N1 + N2)
#define PREP_TOT (PREP_T1 + PREP_T2 + PREP_T3 + PREP_T4)

__global__ void prep_kernel(const float* __restrict__ x,
                            const float* __restrict__ W1l,
                            const float* __restrict__ W1r,
                            const float* __restrict__ resW,
                            const float* __restrict__ W2l,
                            const float* __restrict__ W2r,
                            const float* __restrict__ b1l,
                            const float* __restrict__ b1r,
                            const float* __restrict__ resb,
                            const float* __restrict__ b2l,
                            const float* __restrict__ b2r) {
    size_t id = (size_t)blockIdx.x * blockDim.x + threadIdx.x;
    if (id < PREP_T1) {
        size_t i4 = id;
        size_t row = i4 / (DIN / 4);
        float4 v;
        if (row < NP) v = *reinterpret_cast<const float4*>(x + i4 * 4);
        else          v = make_float4(0.f, 0.f, 0.f, 0.f);
        __half2 h0 = make_half2(__float2half_rn(v.x), __float2half_rn(v.y));
        __half2 h1 = make_half2(__float2half_rn(v.z), __float2half_rn(v.w));
        *reinterpret_cast<__half2*>(g_x16 + i4 * 4)     = h0;
        *reinterpret_cast<__half2*>(g_x16 + i4 * 4 + 2) = h1;
        return;
    }
    id -= PREP_T1;
    if (id < PREP_T2) {
        int i4 = (int)id;
        int k = i4 / (N1 / 4);
        int c = (i4 % (N1 / 4)) * 4;
        const float* W = (c < 256) ? W1l : (c < 512 ? W1r : resW);
        int cc = c & 255;
        float4 v = *reinterpret_cast<const float4*>(W + (size_t)k * 256 + cc);
        size_t o = (size_t)k * N1 + c;
        g_w1[o+0] = __float2half_rn(v.x);
        g_w1[o+1] = __float2half_rn(v.y);
        g_w1[o+2] = __float2half_rn(v.z);
        g_w1[o+3] = __float2half_rn(v.w);
        return;
    }
    id -= PREP_T2;
    if (id < PREP_T3) {
        int i4 = (int)id;
        int k = i4 / (N2 / 4);
        int c = (i4 % (N2 / 4)) * 4;
        const float* W = (c < 256) ? W2l : W2r;
        int cc = c & 255;
        float4 v = *reinterpret_cast<const float4*>(W + (size_t)k * 256 + cc);
        size_t o = (size_t)k * N2 + c;
        g_w2[o+0] = __float2half_rn(v.x);
        g_w2[o+1] = __float2half_rn(v.y);
        g_w2[o+2] = __float2half_rn(v.z);
        g_w2[o+3] = __float2half_rn(v.w);
        return;
    }
    id -= PREP_T3;
    if (id < PREP_T4) {
        int c = (int)id;
        if (c < N1) {
            g_b1[c] = (c < 256) ? b1l[c] : (c < 512 ? b1r[c - 256] : resb[c - 512]);
        } else {
            int c2 = c - N1;
            g_b2[c2] = (c2 < 256) ? b2l[c2] : b2r[c2 - 256];
        }
    }
}

// ---------------- fp16 tensor-core GEMM with fused bias + fp16 epilogue ------
// Yh[M,N] = fp16(A[M,K] @ B[K,N] + bias[N]).
// CTA 128x128, BK=64, 128 threads = 4 warps (2M x 2N), warp tile 64x64,
// 3-stage cp.async, 105 KB smem -> 2 CTAs/SM.
#define GBM 128
#define GBN 128
#define GBK 64
#define GTHREADS 128
#define LDA 72      // 64 + 8 pad (halfs)
#define LDB 136     // 128 + 8 pad
#define STG_A (128 * LDA)
#define STG_B (64 * LDB)
#define STAGE_ELEMS (STG_A + STG_B)
#define NSTAGE 3
#define GEMM_SMEM_BYTES (NSTAGE * STAGE_ELEMS * 2)   // 107520 B
#define LDY 136     // fp32 epilogue pitch; 128*136*4 = 69632 <= GEMM_SMEM_BYTES

__device__ __forceinline__ void gemm_load_stage(
    __half* st,
    const __half* __restrict__ A, const __half* __restrict__ B,
    int bm, int bn, int k0, int K, int N, int tid)
{
    __half* sA = st;
    __half* sB = st + STG_A;
#pragma unroll
    for (int c = 0; c < 8; c++) {
        int idx = tid + c * GTHREADS;
        int row = idx >> 3;
        int col = (idx & 7) * 8;
        size_t g = (size_t)(bm + row) * K + k0 + col;
        cp16(sA + row * LDA + col, A + g);
    }
#pragma unroll
    for (int c = 0; c < 8; c++) {
        int idx = tid + c * GTHREADS;
        int row = idx >> 4;
        int col = (idx & 15) * 8;
        size_t g = (size_t)(k0 + row) * N + bn + col;
        cp16(sB + row * LDB + col, B + g);
    }
    asm volatile("cp.async.commit_group;\n");
}

__global__ __launch_bounds__(GTHREADS, 2)
void gemm_h16(const __half* __restrict__ A,
              const __half* __restrict__ B,
              const float* __restrict__ bias,      // length N, added pre-convert
              __half* __restrict__ Yh,             // fp16 out, pitch N
              int K, int N)
{
    extern __shared__ __half smem[];
    const int tid = threadIdx.x;
    const int bm = blockIdx.y * GBM;
    const int bn = blockIdx.x * GBN;
    const int warp = tid >> 5;
    const int wm = (warp >> 1) * 64;   // 0 or 64
    const int wn = (warp & 1) * 64;    // 0 or 64

    wmma::fragment<wmma::accumulator, 16, 16, 16, float> acc[4][4];
#pragma unroll
    for (int i = 0; i < 4; i++)
#pragma unroll
        for (int j = 0; j < 4; j++) wmma::fill_fragment(acc[i][j], 0.f);

    const int KT = K / GBK;            // >= 4 for both GEMMs
    gemm_load_stage(smem + 0 * STAGE_ELEMS, A, B, bm, bn, 0 * GBK, K, N, tid);
    gemm_load_stage(smem + 1 * STAGE_ELEMS, A, B, bm, bn, 1 * GBK, K, N, tid);

    for (int kt = 0; kt < KT; kt++) {
        if (kt + 1 < KT) asm volatile("cp.async.wait_group 1;\n" ::: "memory");
        else             asm volatile("cp.async.wait_group 0;\n" ::: "memory");
        __syncthreads();
        if (kt + 2 < KT)
            gemm_load_stage(smem + ((kt + 2) % NSTAGE) * STAGE_ELEMS,
                            A, B, bm, bn, (kt + 2) * GBK, K, N, tid);

        __half* st = smem + (kt % NSTAGE) * STAGE_ELEMS;
        const __half* sA = st;
        const __half* sB = st + STG_A;

#pragma unroll
        for (int ks = 0; ks < 4; ks++) {
            wmma::fragment<wmma::matrix_a, 16, 16, 16, __half, wmma::row_major> fa[4];
#pragma unroll
            for (int i = 0; i < 4; i++)
                wmma::load_matrix_sync(fa[i], sA + (wm + i * 16) * LDA + ks * 16, LDA);
#pragma unroll
            for (int j = 0; j < 4; j++) {
                wmma::fragment<wmma::matrix_b, 16, 16, 16, __half, wmma::row_major> fb;
                wmma::load_matrix_sync(fb, sB + ks * 16 * LDB + wn + j * 16, LDB);
#pragma unroll
                for (int i = 0; i < 4; i++)
                    wmma::mma_sync(acc[i][j], fa[i], fb, acc[i][j]);
            }
        }
    }

    // ---- fused bias + fp16 epilogue via smem staging ----
    __syncthreads();                         // all stage reads complete
    float* sY = reinterpret_cast<float*>(smem);
#pragma unroll
    for (int i = 0; i < 4; i++)
#pragma unroll
        for (int j = 0; j < 4; j++)
            wmma::store_matrix_sync(sY + (wm + i * 16) * LDY + wn + j * 16,
                                    acc[i][j], LDY, wmma::mem_row_major);
    __syncthreads();

#pragma unroll
    for (int c = 0; c < 16; c++) {
        int idx = tid + c * GTHREADS;        // 2048 chunks of 8 cols
        int row = idx >> 4;
        int col = (idx & 15) * 8;
        int grow = bm + row;
        if (grow >= NP) continue;            // pad rows never consumed
        const float* src = sY + row * LDY + col;
        float4 v0 = *reinterpret_cast<const float4*>(src);
        float4 v1 = *reinterpret_cast<const float4*>(src + 4);
        float4 b0 = *reinterpret_cast<const float4*>(bias + bn + col);
        float4 b1 = *reinterpret_cast<const float4*>(bias + bn + col + 4);
        v0.x += b0.x; v0.y += b0.y; v0.z += b0.z; v0.w += b0.w;
        v1.x += b1.x; v1.y += b1.y; v1.z += b1.z; v1.w += b1.w;
        __half2 h[4];
        h[0] = make_half2(__float2half_rn(v0.x), __float2half_rn(v0.y));
        h[1] = make_half2(__float2half_rn(v0.z), __float2half_rn(v0.w));
        h[2] = make_half2(__float2half_rn(v1.x), __float2half_rn(v1.y));
        h[3] = make_half2(__float2half_rn(v1.z), __float2half_rn(v1.w));
        *reinterpret_cast<uint4*>(Yh + (size_t)grow * N + bn + col) =
            *reinterpret_cast<uint4*>(h);
    }
}

// ---------------- CSR build --------------------------------------------------
__global__ void zero_deg_kernel() {
    int i = blockIdx.x * blockDim.x + threadIdx.x;
    if (i < NP) g_deg[i] = 0;
}

__global__ void count_deg_kernel(const int* __restrict__ dst) {
    int e = blockIdx.x * blockDim.x + threadIdx.x;
    if (e < NE) atomicAdd(&g_deg[dst[e]], 1);
}

__global__ void build_offsets_kernel() {
    __shared__ int ssum[1024];
    const int tid = threadIdx.x;
    const int CHK = (NP + 1023) / 1024;
    int start = tid * CHK;
    int end = start + CHK; if (end > NP) end = NP;
    if (start > NP) start = NP;

    int s = 0;
    for (int i = start; i < end; i++) s += g_deg[i];
    ssum[tid] = s;
    __syncthreads();
    for (int o = 1; o < 1024; o <<= 1) {
        int v = (tid >= o) ? ssum[tid - o] : 0;
        __syncthreads();
        ssum[tid] += v;
        __syncthreads();
    }
    int run = (tid == 0) ? 0 : ssum[tid - 1];
    for (int i = start; i < end; i++) {
        g_off[i] = run;
        g_cur[i] = run;
        run += g_deg[i];
    }
    if (tid == 1023) g_off[NP] = ssum[1023];
}

__global__ void scatter_edges_kernel(const int* __restrict__ src,
                                     const int* __restrict__ dst) {
    int e = blockIdx.x * blockDim.x + threadIdx.x;
    if (e < NE) {
        int d = dst[e];
        int pos = atomicAdd(&g_cur[d], 1);
        g_srcs[pos] = src[e];
    }
}

// ---------------- fused GATv2 gather + softmax + LN/ELU epilogue -------------
// Biases pre-folded into y*h by the GEMM epilogue. 4-edge unrolled online
// softmax (MLP=4). `ld` = row pitch (768 layer1, 512 layer2).
__device__ __forceinline__ void load8h(const __half* p, float* f) {
    uint4 u = *reinterpret_cast<const uint4*>(p);
    const __half2* h = reinterpret_cast<const __half2*>(&u);
    float2 t;
    t = __half22float2(h[0]); f[0] = t.x; f[1] = t.y;
    t = __half22float2(h[1]); f[2] = t.x; f[3] = t.y;
    t = __half22float2(h[2]); f[4] = t.x; f[5] = t.y;
    t = __half22float2(h[3]); f[6] = t.x; f[7] = t.y;
}

__device__ __forceinline__ float edge_score(const float* xlj, const float* xri,
                                            const float* atv) {
    float p = 0.f;
#pragma unroll
    for (int k = 0; k < 8; k++) {
        float t = xlj[k] + xri[k];
        t = (t > 0.f) ? t : NEG_SLOPE * t;
        p = fmaf(atv[k], t, p);
    }
    p += __shfl_xor_sync(0xffffffffu, p, 8, 16);
    p += __shfl_xor_sync(0xffffffffu, p, 4, 16);
    p += __shfl_xor_sync(0xffffffffu, p, 2, 16);
    p += __shfl_xor_sync(0xffffffffu, p, 1, 16);
    return p;
}

__device__ __forceinline__ void gat_core(const __half* __restrict__ yh, int ld,
                                         const float* __restrict__ att,
                                         const float* __restrict__ bias,
                                         int i, int lane, float* v /*out[8]*/) {
    const int cbase = lane * 8;
    float xri[8], atv[8];
    {
        load8h(yh + (size_t)i * ld + 256 + cbase, xri);   // biased xr[i]
        float4 t0 = *reinterpret_cast<const float4*>(att + cbase);
        float4 t1 = *reinterpret_cast<const float4*>(att + cbase + 4);
        atv[0]=t0.x; atv[1]=t0.y; atv[2]=t0.z; atv[3]=t0.w;
        atv[4]=t1.x; atv[5]=t1.y; atv[6]=t1.z; atv[7]=t1.w;
    }

    // init with self loop (biased xl[i])
    float m, s, acc[8];
    {
        float xls[8];
        load8h(yh + (size_t)i * ld + cbase, xls);
        m = edge_score(xls, xri, atv);
        s = 1.f;
#pragma unroll
        for (int k = 0; k < 8; k++) acc[k] = xls[k];
    }

    int ptr = g_off[i];
    const int end = g_off[i + 1];

    for (; ptr + 4 <= end; ptr += 4) {
        int j0 = g_srcs[ptr + 0];
        int j1 = g_srcs[ptr + 1];
        int j2 = g_srcs[ptr + 2];
        int j3 = g_srcs[ptr + 3];
        uint4 u0 = *reinterpret_cast<const uint4*>(yh + (size_t)j0 * ld + cbase);
        uint4 u1 = *reinterpret_cast<const uint4*>(yh + (size_t)j1 * ld + cbase);
        uint4 u2 = *reinterpret_cast<const uint4*>(yh + (size_t)j2 * ld + cbase);
        uint4 u3 = *reinterpret_cast<const uint4*>(yh + (size_t)j3 * ld + cbase);
        float x0[8], x1[8], x2[8], x3[8];
        load8h(reinterpret_cast<const __half*>(&u0), x0);
        load8h(reinterpret_cast<const __half*>(&u1), x1);
        load8h(reinterpret_cast<const __half*>(&u2), x2);
        load8h(reinterpret_cast<const __half*>(&u3), x3);
        float e0 = edge_score(x0, xri, atv);
        float e1 = edge_score(x1, xri, atv);
        float e2 = edge_score(x2, xri, atv);
        float e3 = edge_score(x3, xri, atv);

        float nm = fmaxf(fmaxf(m, fmaxf(e0, e1)), fmaxf(e2, e3));
        float sc = __expf(m - nm);
        float w0 = __expf(e0 - nm);
        float w1 = __expf(e1 - nm);
        float w2 = __expf(e2 - nm);
        float w3 = __expf(e3 - nm);
        s = s * sc + (w0 + w1) + (w2 + w3);
#pragma unroll
        for (int k = 0; k < 8; k++) {
            float t = fmaf(w0, x0[k], w1 * x1[k]) + fmaf(w2, x2[k], w3 * x3[k]);
            acc[k] = fmaf(acc[k], sc, t);
        }
        m = nm;
    }
    for (; ptr < end; ptr++) {
        int j0 = g_srcs[ptr];
        float x0[8];
        load8h(yh + (size_t)j0 * ld + cbase, x0);
        float e0 = edge_score(x0, xri, atv);
        float nm = fmaxf(m, e0);
        float sc = __expf(m - nm);
        float w0 = __expf(e0 - nm);
        s = s * sc + w0;
#pragma unroll
        for (int k = 0; k < 8; k++) acc[k] = fmaf(acc[k], sc, w0 * x0[k]);
        m = nm;
    }

    float inv = 1.f / s;
#pragma unroll
    for (int k = 0; k < 8; k++)
        v[k] = acc[k] * inv + bias[cbase + k];   // attention output bias
}

__device__ __forceinline__ void ln_elu_inplace(float* v,
                                               const float* __restrict__ g,
                                               const float* __restrict__ b,
                                               int lane) {
    float s = 0.f, s2 = 0.f;
#pragma unroll
    for (int k = 0; k < 8; k++) { s += v[k]; s2 = fmaf(v[k], v[k], s2); }
#pragma unroll
    for (int o = 16; o >= 1; o >>= 1) {
        s  += __shfl_xor_sync(0xffffffffu, s,  o);
        s2 += __shfl_xor_sync(0xffffffffu, s2, o);
    }
    float mu  = s * (1.f / 256.f);
    float var = s2 * (1.f / 256.f) - mu * mu;
    float rs  = rsqrtf(var + 1e-5f);
#pragma unroll
    for (int k = 0; k < 8; k++) {
        int c = lane * 8 + k;
        float t = (v[k] - mu) * rs * g[c] + b[c];
        v[k] = (t > 0.f) ? t : expm1f(t);
    }
}

// layer 1: gather -> LN -> ELU -> + res (fp16, resb folded) -> h116; pads zeroed
__global__ void gat1_kernel(const float* __restrict__ att,
                            const float* __restrict__ bias,
                            const float* __restrict__ lng,
                            const float* __restrict__ lnb,
                            __half* __restrict__ h116) {
    int w = (blockIdx.x * blockDim.x + threadIdx.x) >> 5;
    int lane = threadIdx.x & 31;
    if (w >= MPAD) return;
    const int cbase = lane * 8;
    if (w >= NP) {      // zero the GEMM2 pad rows
#pragma unroll
        for (int k = 0; k < 8; k++)
            h116[(size_t)w * DOUT + cbase + k] = __float2half_rn(0.f);
        return;
    }
    float v[8];
    gat_core(g_y1h, N1, att, bias, w, lane, v);
    ln_elu_inplace(v, lng, lnb, lane);
    float resv[8];
    load8h(g_y1h + (size_t)w * N1 + 512 + cbase, resv);   // fp16 residual (+resb)
#pragma unroll
    for (int k = 0; k < 8; k++) {
        size_t idx = (size_t)w * DOUT + cbase + k;
        h116[idx] = __float2half_rn(v[k] + resv[k]);
    }
}

// layer 2: gather -> LN -> ELU -> + h1 (fp16) -> JK max
__global__ void gat2_kernel(const float* __restrict__ att,
                            const float* __restrict__ bias,
                            const float* __restrict__ lng,
                            const float* __restrict__ lnb,
                            const __half* __restrict__ h116,
                            float* __restrict__ out) {
    int w = (blockIdx.x * blockDim.x + threadIdx.x) >> 5;
    int lane = threadIdx.x & 31;
    if (w >= NP) return;
    float v[8];
    gat_core(g_y2h, N2, att, bias, w, lane, v);
    ln_elu_inplace(v, lng, lnb, lane);
    const int cbase = lane * 8;
    float h1v[8];
    load8h(h116 + (size_t)w * DOUT + cbase, h1v);
#pragma unroll
    for (int k = 0; k < 8; k++) {
        size_t idx = (size_t)w * DOUT + cbase + k;
        out[idx] = fmaxf(h1v[k], v[k] + h1v[k]);
    }
}

// ---------------- launch -----------------------------------------------------
extern "C" void kernel_launch(void* const* d_in, const int* in_sizes, int n_in,
                              void* d_out, int out_size) {
    const float* x     = (const float*)d_in[0];
    const int*   ei    = (const int*)  d_in[1];
    const float* W1l   = (const float*)d_in[2];
    const float* b1l   = (const float*)d_in[3];
    const float* W1r   = (const float*)d_in[4];
    const float* b1r   = (const float*)d_in[5];
    const float* att1  = (const float*)d_in[6];
    const float* bias1 = (const float*)d_in[7];
    const float* W2l   = (const float*)d_in[8];
    const float* b2l   = (const float*)d_in[9];
    const float* W2r   = (const float*)d_in[10];
    const float* b2r   = (const float*)d_in[11];
    const float* att2  = (const float*)d_in[12];
    const float* bias2 = (const float*)d_in[13];
    const float* ln1g  = (const float*)d_in[14];
    const float* ln1b  = (const float*)d_in[15];
    const float* ln2g  = (const float*)d_in[16];
    const float* ln2b  = (const float*)d_in[17];
    const float* resW  = (const float*)d_in[18];
    const float* resb  = (const float*)d_in[19];
    float* out = (float*)d_out;

    const int* e_src = ei;
    const int* e_dst = ei + NE;

    __half *x16, *w1, *w2, *h116, *y1h, *y2h;
    float *bv1, *bv2;
    cudaGetSymbolAddress((void**)&x16,  g_x16);
    cudaGetSymbolAddress((void**)&w1,   g_w1);
    cudaGetSymbolAddress((void**)&w2,   g_w2);
    cudaGetSymbolAddress((void**)&h116, g_h116);
    cudaGetSymbolAddress((void**)&y1h,  g_y1h);
    cudaGetSymbolAddress((void**)&y2h,  g_y2h);
    cudaGetSymbolAddress((void**)&bv1,  g_b1);
    cudaGetSymbolAddress((void**)&bv2,  g_b2);

    cudaFuncSetAttribute(gemm_h16, cudaFuncAttributeMaxDynamicSharedMemorySize,
                         GEMM_SMEM_BYTES);

    // one-time handles (host-side only; identical launched work every call)
    static cudaStream_t s2 = [] { cudaStream_t s; cudaStreamCreateWithFlags(&s, cudaStreamNonBlocking); return s; }();
    static cudaEvent_t  e1 = [] { cudaEvent_t e; cudaEventCreateWithFlags(&e, cudaEventDisableTiming); return e; }();
    static cudaEvent_t  e2 = [] { cudaEvent_t e; cudaEventCreateWithFlags(&e, cudaEventDisableTiming); return e; }();

    // ---- fork: CSR chain on s2 (independent of prep/GEMM1) ----
    cudaEventRecord(e1, 0);
    cudaStreamWaitEvent(s2, e1, 0);
    zero_deg_kernel<<<(NP + 255) / 256, 256, 0, s2>>>();
    count_deg_kernel<<<(NE + 255) / 256, 256, 0, s2>>>(e_dst);
    build_offsets_kernel<<<1, 1024, 0, s2>>>();
    scatter_edges_kernel<<<(NE + 255) / 256, 256, 0, s2>>>(e_src, e_dst);
    cudaEventRecord(e2, s2);

    // ---- main chain: prep -> GEMM1 (concurrent with CSR) ----
    prep_kernel<<<(unsigned)((PREP_TOT + 255) / 256), 256>>>(
        x, W1l, W1r, resW, W2l, W2r, b1l, b1r, resb, b2l, b2r);
    gemm_h16<<<dim3(N1 / GBN, MPAD / GBM), GTHREADS, GEMM_SMEM_BYTES>>>(
        x16, w1, bv1, y1h, DIN, N1);

    // ---- join: gat1 needs the CSR ----
    cudaStreamWaitEvent(0, e2, 0);

    int gather1Blocks = (MPAD * 32 + 255) / 256;
    int gather2Blocks = (NP * 32 + 255) / 256;
    gat1_kernel<<<gather1Blocks, 256>>>(att1, bias1, ln1g, ln1b, h116);

    // layer-2 fused GEMM: all cols -> fp16 g_y2h (biases folded)
    gemm_h16<<<dim3(N2 / GBN, MPAD / GBM), GTHREADS, GEMM_SMEM_BYTES>>>(
        h116, w2, bv2, y2h, DOUT, N2);

    // layer-2 gather + LN/ELU + JK-max (fused)
    gat2_kernel<<<gather2Blocks, 256>>>(att2, bias2, ln2g, ln2b, h116, out);
}